// round 7
// baseline (speedup 1.0000x reference)
#include <cuda_runtime.h>
#include <cuda_bf16.h>
#include <cstdint>
#include <math.h>

// Problem constants
#define NB 32768   // batch
#define TT 9       // time steps (T-1)
#define DD 81      // input dim
#define HH 128     // hidden
#define NG 512     // 4*HH gates
#define KW 96      // w_in K padded (81 -> 96)
#define KT 224     // weight k-cols (96 w_in + 128 h)

// Tiling
#define BM 64      // batch rows per CTA
#define AST 464    // A row stride bytes (224 bf16 used; 464 mod 128 = 80 -> conflict-free)
#define BSTW 208   // B w_in slot row stride (96 bf16 = 192B used)
#define BSTH 272   // B h slot row stride (128 bf16 = 256B used)

// SMEM map (bytes)
#define SM_BIAS 0          // 512 f32 = 2048
#define SM_A_HI 2048       // 64*464 = 29696
#define SM_A_LO 31744      // 29696
#define SM_B0H  61440      // 128*208 = 26624 (w_in weights hi)
#define SM_B0L  88064      // 26624
#define SM_B1H  114688     // 128*272 = 34816 (h weights hi)
#define SM_B1L  149504     // 34816
#define SM_TOTAL 184320

// device scratch: weights pre-split bf16 hi/lo, row-major [n][224]
__device__ __align__(16) __nv_bfloat16 g_Bh[NG * KT];
__device__ __align__(16) __nv_bfloat16 g_Bl[NG * KT];
__device__ float g_bias[NG];

// ---------------------------------------------------------------------------
// prep: split weights into bf16 hi/lo, layout [n][k=224]; fuse biases.
// ---------------------------------------------------------------------------
__global__ void prep_kernel(const float* __restrict__ W_ih,
                            const float* __restrict__ W_hh,
                            const float* __restrict__ b_ih,
                            const float* __restrict__ b_hh) {
    int idx = blockIdx.x * blockDim.x + threadIdx.x;   // 512*224
    if (idx < NG * KT) {
        int n = idx / KT;
        int k = idx - n * KT;
        float w = 0.f;
        if (k < DD) w = W_ih[n * DD + k];
        else if (k >= KW) w = W_hh[n * HH + (k - KW)];
        __nv_bfloat16 hi = __float2bfloat16(w);
        __nv_bfloat16 lo = __float2bfloat16(w - __bfloat162float(hi));
        g_Bh[idx] = hi;
        g_Bl[idx] = lo;
    }
    if (idx < NG) g_bias[idx] = b_ih[idx] + b_hh[idx];
}

// ---------------------------------------------------------------------------
// attention: softmax over d of (sum_t x[b,t,d]*Wx[t]); write input_weighted.
// ---------------------------------------------------------------------------
__global__ void attn_kernel(const float* __restrict__ x,
                            const float* __restrict__ W_attn,
                            float* __restrict__ out_w) {
    int gw = (blockIdx.x * blockDim.x + threadIdx.x) >> 5;
    int lane = threadIdx.x & 31;
    if (gw >= NB) return;

    float wx[TT];
#pragma unroll
    for (int tt = 0; tt < TT; tt++) wx[tt] = W_attn[2 * HH + tt];

    const float* xb = x + (size_t)gw * TT * DD;
    float xr[3][TT];
    float pre[3];
#pragma unroll
    for (int ii = 0; ii < 3; ii++) {
        int d = lane + 32 * ii;
        float p = 0.f;
#pragma unroll
        for (int tt = 0; tt < TT; tt++) {
            float v = (d < DD) ? xb[tt * DD + d] : 0.f;
            xr[ii][tt] = v;
            p = fmaf(v, wx[tt], p);
        }
        pre[ii] = (d < DD) ? p : -3.0e38f;
    }
    float mx = fmaxf(pre[0], fmaxf(pre[1], pre[2]));
#pragma unroll
    for (int o = 16; o > 0; o >>= 1) mx = fmaxf(mx, __shfl_xor_sync(0xffffffffu, mx, o));

    float ev[3];
    float s = 0.f;
#pragma unroll
    for (int ii = 0; ii < 3; ii++) {
        int d = lane + 32 * ii;
        ev[ii] = (d < DD) ? __expf(pre[ii] - mx) : 0.f;
        s += ev[ii];
    }
#pragma unroll
    for (int o = 16; o > 0; o >>= 1) s += __shfl_xor_sync(0xffffffffu, s, o);
    float inv = 1.f / s;

    float* ob = out_w + (size_t)gw * TT * DD;
#pragma unroll
    for (int ii = 0; ii < 3; ii++) {
        int d = lane + 32 * ii;
        if (d < DD) {
            float a = ev[ii] * inv;
#pragma unroll
            for (int tt = 0; tt < TT; tt++) ob[tt * DD + d] = a * xr[ii][tt];
        }
    }
}

// ---------------------------------------------------------------------------
// helpers
// ---------------------------------------------------------------------------
__device__ __forceinline__ uint32_t smem_u32(const void* p) {
    uint32_t a;
    asm("{ .reg .u64 t; cvta.to.shared.u64 t, %1; cvt.u32.u64 %0, t; }" : "=r"(a) : "l"(p));
    return a;
}
__device__ __forceinline__ void ldsm_x4(uint32_t addr, uint32_t* r) {
    asm volatile("ldmatrix.sync.aligned.m8n8.x4.shared.b16 {%0,%1,%2,%3}, [%4];"
                 : "=r"(r[0]), "=r"(r[1]), "=r"(r[2]), "=r"(r[3]) : "r"(addr));
}
__device__ __forceinline__ void mma16816(float* d, const uint32_t* a, const uint32_t* b) {
    asm volatile(
        "mma.sync.aligned.m16n8k16.row.col.f32.bf16.bf16.f32 "
        "{%0,%1,%2,%3}, {%4,%5,%6,%7}, {%8,%9}, {%0,%1,%2,%3};"
        : "+f"(d[0]), "+f"(d[1]), "+f"(d[2]), "+f"(d[3])
        : "r"(a[0]), "r"(a[1]), "r"(a[2]), "r"(a[3]), "r"(b[0]), "r"(b[1]));
}
__device__ __forceinline__ void cp16(uint32_t dst, const void* src) {
    asm volatile("cp.async.cg.shared.global [%0], [%1], 16;"
                 :: "r"(dst), "l"(__cvta_generic_to_global(src)) : "memory");
}
__device__ __forceinline__ void cp_commit() {
    asm volatile("cp.async.commit_group;" ::: "memory");
}
__device__ __forceinline__ void cp_wait1() {
    asm volatile("cp.async.wait_group 1;" ::: "memory");
}
__device__ __forceinline__ float sigmoidf_(float v) {
    return __fdividef(1.f, 1.f + __expf(-v));
}
__device__ __forceinline__ float tanhf_(float v) {
    return __fdividef(2.f, 1.f + __expf(-2.f * v)) - 1.f;
}
__device__ __forceinline__ void split_pack(float v0, float v1, uint32_t& h2, uint32_t& l2) {
    __nv_bfloat16 h0 = __float2bfloat16(v0);
    __nv_bfloat16 h1 = __float2bfloat16(v1);
    float r0 = v0 - __bfloat162float(h0);
    float r1 = v1 - __bfloat162float(h1);
    __nv_bfloat162 H(h0, h1);
    __nv_bfloat162 L(__float2bfloat16(r0), __float2bfloat16(r1));
    h2 = *reinterpret_cast<uint32_t*>(&H);
    l2 = *reinterpret_cast<uint32_t*>(&L);
}

// gate order i(0) -> g(2) -> f(1) -> o(3)
__device__ __forceinline__ int gate_of(int cc) {
    return (cc == 0) ? 0 : (cc == 1) ? 2 : (cc == 2) ? 1 : 3;
}

// issue cp.async loads for stream item s (s = t*8 + cc*2 + phase), always commits
__device__ __forceinline__ void issue_item(int s, uint32_t smem_base, int tid) {
    if (s < 8 * TT) {
        const int phase = s & 1;
        const int q = gate_of((s >> 1) & 3);
        if (phase == 0) {
#pragma unroll
            for (int it = 0; it < 6; it++) {         // 128*12 / 256
                int i = it * 256 + tid;
                int n = i / 12, ck = i - n * 12;
                size_t sb = ((size_t)(q * 128 + n) * KT) * 2 + ck * 16;
                cp16(smem_base + SM_B0H + n * BSTW + ck * 16, (const char*)g_Bh + sb);
                cp16(smem_base + SM_B0L + n * BSTW + ck * 16, (const char*)g_Bl + sb);
            }
        } else {
#pragma unroll
            for (int it = 0; it < 8; it++) {         // 128*16 / 256
                int i = it * 256 + tid;
                int n = i / 16, ck = i - n * 16;
                size_t sb = ((size_t)(q * 128 + n) * KT + KW) * 2 + ck * 16;
                cp16(smem_base + SM_B1H + n * BSTH + ck * 16, (const char*)g_Bh + sb);
                cp16(smem_base + SM_B1L + n * BSTH + ck * 16, (const char*)g_Bl + sb);
            }
        }
    }
    cp_commit();
}

// prefetch w_in tile (step t) into registers: 24 values/thread (64 rows x 96 padded)
__device__ __forceinline__ void ldg_win(const float* __restrict__ out_w,
                                        int b0, int t, int tid, float* wr) {
#pragma unroll
    for (int i = 0; i < 24; i++) {
        int p = i * 256 + tid;
        int m = p / KW;
        int d = p - m * KW;
        wr[i] = (d < DD) ? out_w[(((size_t)(b0 + m)) * TT + t) * DD + d] : 0.f;
    }
}
// convert + store w_in regs into A (bf16 hi/lo)
__device__ __forceinline__ void store_win(char* smem_c, int tid, const float* wr) {
#pragma unroll
    for (int i = 0; i < 24; i++) {
        int p = i * 256 + tid;
        int m = p / KW;
        int d = p - m * KW;
        __nv_bfloat16 hi = __float2bfloat16(wr[i]);
        __nv_bfloat16 lo = __float2bfloat16(wr[i] - __bfloat162float(hi));
        *(__nv_bfloat16*)(smem_c + SM_A_HI + m * AST + d * 2) = hi;
        *(__nv_bfloat16*)(smem_c + SM_A_LO + m * AST + d * 2) = lo;
    }
}

// one GEMM phase: 2 m-tiles x 4 n-tiles, 3-term split, B via ldmatrix x4
__device__ __forceinline__ void mma_phase64(float acc[2][4][4],
                                            uint32_t aHi, uint32_t aLo,
                                            uint32_t bHi, uint32_t bLo,
                                            int bst, int nsteps) {
#pragma unroll 1
    for (int j = 0; j < nsteps; j++) {
        uint32_t bh[4][2], bl[4][2];
#pragma unroll
        for (int pr = 0; pr < 2; pr++) {
            uint32_t r4[4];
            ldsm_x4(bHi + pr * 16 * bst + j * 32, r4);
            bh[pr * 2][0] = r4[0]; bh[pr * 2][1] = r4[1];
            bh[pr * 2 + 1][0] = r4[2]; bh[pr * 2 + 1][1] = r4[3];
            ldsm_x4(bLo + pr * 16 * bst + j * 32, r4);
            bl[pr * 2][0] = r4[0]; bl[pr * 2][1] = r4[1];
            bl[pr * 2 + 1][0] = r4[2]; bl[pr * 2 + 1][1] = r4[3];
        }
#pragma unroll
        for (int im = 0; im < 2; im++) {
            uint32_t ah[4], al[4];
            ldsm_x4(aHi + im * 16 * AST + j * 32, ah);
            ldsm_x4(aLo + im * 16 * AST + j * 32, al);
#pragma unroll
            for (int in = 0; in < 4; in++) {
                mma16816(acc[im][in], ah, bh[in]);
                mma16816(acc[im][in], ah, bl[in]);
                mma16816(acc[im][in], al, bh[in]);
            }
        }
    }
}

// ---------------------------------------------------------------------------
// recurrent HMMA kernel: 1 CTA = 64 batch rows, 256 threads, cp.async pipeline
// ---------------------------------------------------------------------------
__global__ __launch_bounds__(256, 1)
void rnn_tc_kernel(const float* __restrict__ out_w, float* __restrict__ out_enc) {
    extern __shared__ char smem_c[];
    const uint32_t smem_base = smem_u32(smem_c);
    const int tid = threadIdx.x;
    const int wid = tid >> 5;
    const int lane = tid & 31;
    const int mw = wid & 1;        // 2 m-warps (rows 32*mw..)
    const int nw = wid >> 1;       // 4 n-warps (cols 32*nw..)
    const int b0 = blockIdx.x * BM;

    float* bias_s = (float*)(smem_c + SM_BIAS);
    for (int i = tid; i < NG; i += 256) bias_s[i] = g_bias[i];

    // lane-resolved ldmatrix bases
    const uint32_t aHiB = smem_base + SM_A_HI + (mw * 32 + (lane & 15)) * AST
                        + ((lane >> 4) & 1) * 16;
    const uint32_t aLoB = aHiB + (SM_A_LO - SM_A_HI);
    const int brow = (lane & 7) + ((lane >> 4) & 1) * 8;
    const int bk16 = ((lane >> 3) & 1) * 16;
    const uint32_t b0HiB = smem_base + SM_B0H + (nw * 32 + brow) * BSTW + bk16;
    const uint32_t b0LoB = b0HiB + (SM_B0L - SM_B0H);
    const uint32_t b1HiB = smem_base + SM_B1H + (nw * 32 + brow) * BSTH + bk16;
    const uint32_t b1LoB = b1HiB + (SM_B1L - SM_B1H);

    float c_r[2][4][4];
    float tmp[2][4][4];
#pragma unroll
    for (int im = 0; im < 2; im++)
#pragma unroll
        for (int in = 0; in < 4; in++)
#pragma unroll
            for (int r = 0; r < 4; r++) c_r[im][in][r] = 0.f;

    // prime: w_in regs for t=0, first two B items in flight
    float wr[24];
    ldg_win(out_w, b0, 0, tid, wr);
    issue_item(0, smem_base, tid);
    issue_item(1, smem_base, tid);

    for (int t = 0; t < TT; t++) {
        store_win(smem_c, tid, wr);    // A w_in for this step (ordered by next barrier)

#pragma unroll 1
        for (int cc = 0; cc < 4; cc++) {
            const int q = gate_of(cc);
            const int s0 = t * 8 + cc * 2;

            float acc[2][4][4];
#pragma unroll
            for (int im = 0; im < 2; im++)
#pragma unroll
                for (int in = 0; in < 4; in++)
#pragma unroll
                    for (int r = 0; r < 4; r++) acc[im][in][r] = 0.f;

            // ---- phase 0: w_in GEMM (k 0..95) ----
            cp_wait1();
            __syncthreads();
            mma_phase64(acc, aHiB, aLoB, b0HiB, b0LoB, BSTW, KW / 16);
            __syncthreads();
            issue_item(s0 + 2, smem_base, tid);

            // ---- phase 1: h GEMM (k 96..223), skip at t=0 ----
            cp_wait1();
            __syncthreads();
            if (t > 0)
                mma_phase64(acc, aHiB + 192, aLoB + 192, b1HiB, b1LoB, BSTH, HH / 16);
            __syncthreads();
            issue_item(s0 + 3, smem_base, tid);

            // prefetch next step's w_in during the last epilogue
            if (cc == 3 && t + 1 < TT) ldg_win(out_w, b0, t + 1, tid, wr);

            // ---- elementwise on gate q ----
#pragma unroll
            for (int im = 0; im < 2; im++) {
#pragma unroll
                for (int in = 0; in < 4; in++) {
#pragma unroll
                    for (int rh = 0; rh < 2; rh++) {
                        const int m = mw * 32 + im * 16 + (lane >> 2) + rh * 8;
                        const int n0 = nw * 32 + in * 8 + (lane & 3) * 2;
                        float g0 = acc[im][in][rh * 2]     + bias_s[q * HH + n0];
                        float g1 = acc[im][in][rh * 2 + 1] + bias_s[q * HH + n0 + 1];
                        if (q == 0) {
                            tmp[im][in][rh * 2]     = sigmoidf_(g0);
                            tmp[im][in][rh * 2 + 1] = sigmoidf_(g1);
                        } else if (q == 2) {
                            tmp[im][in][rh * 2]     *= tanhf_(g0);
                            tmp[im][in][rh * 2 + 1] *= tanhf_(g1);
                        } else if (q == 1) {
                            c_r[im][in][rh * 2] =
                                sigmoidf_(g0) * c_r[im][in][rh * 2] + tmp[im][in][rh * 2];
                            c_r[im][in][rh * 2 + 1] =
                                sigmoidf_(g1) * c_r[im][in][rh * 2 + 1] + tmp[im][in][rh * 2 + 1];
                        } else {
                            float h0 = sigmoidf_(g0) * tanhf_(c_r[im][in][rh * 2]);
                            float h1 = sigmoidf_(g1) * tanhf_(c_r[im][in][rh * 2 + 1]);
                            *(float2*)(out_enc + (((size_t)(b0 + m)) * TT + t) * HH + n0) =
                                make_float2(h0, h1);
                            if (t + 1 < TT) {
                                uint32_t h2, l2;
                                split_pack(h0, h1, h2, l2);
                                *(uint32_t*)(smem_c + SM_A_HI + m * AST + (KW + n0) * 2) = h2;
                                *(uint32_t*)(smem_c + SM_A_LO + m * AST + (KW + n0) * 2) = l2;
                            }
                        }
                    }
                }
            }
        }
    }
}

// ---------------------------------------------------------------------------
extern "C" void kernel_launch(void* const* d_in, const int* in_sizes, int n_in,
                              void* d_out, int out_size) {
    const float* x      = (const float*)d_in[0];
    const float* W_attn = (const float*)d_in[1];
    // d_in[2] = b_attn: cancels in softmax, unused
    const float* W_ih   = (const float*)d_in[3];
    const float* W_hh   = (const float*)d_in[4];
    const float* b_ih   = (const float*)d_in[5];
    const float* b_hh   = (const float*)d_in[6];

    float* out     = (float*)d_out;
    float* out_w   = out;                           // (B, 9, 81)
    float* out_enc = out + (size_t)NB * TT * DD;    // (B, 9, 128)

    prep_kernel<<<448, 256>>>(W_ih, W_hh, b_ih, b_hh);
    attn_kernel<<<NB / 8, 256>>>(x, W_attn, out_w);

    cudaFuncSetAttribute(rnn_tc_kernel, cudaFuncAttributeMaxDynamicSharedMemorySize, SM_TOTAL);
    rnn_tc_kernel<<<NB / BM, 256, SM_TOTAL>>>(out_w, out_enc);
}